// round 1
// baseline (speedup 1.0000x reference)
#include <cuda_runtime.h>
#include <math.h>

// Problem constants (fixed by setup_inputs)
#define BB   8
#define CC   512
#define SS   256
#define TT   8192
#define DIL  4
#define NTOT (BB*TT)       // 65536
#define K1   (2*CC)        // 1024 : reduction dim of GEMM1 (channels x taps)
#define M2   (CC+SS)       // 768  : rows of GEMM2 (res ++ skip)
#define KB   16            // k-chunk per smem stage

#define SQRT_HALF 0.70710678118654752440f

// ---------------- device scratch (static globals: no allocation allowed) ---
__device__ __align__(16) float g_Wf[K1*CC];     // [k][o]  filter weights, K-major
__device__ __align__(16) float g_Wg[K1*CC];     // [k][o]  gate weights,   K-major
__device__ __align__(16) float g_W2[CC*M2];     // [c][m]  res(0..511) ++ skip(512..767)
__device__ __align__(16) float g_z [BB*CC*TT];  // gated activations [b][c][t]

// ---------------- weight packing -------------------------------------------
// GEMM1 A: row k<512 -> tap1 (x[t]),  k>=512 -> tap0 (x[t-4]);  torch OIH layout in.
__global__ void pack_w1(const float* __restrict__ fw, const float* __restrict__ gw) {
    int idx = blockIdx.x * blockDim.x + threadIdx.x;
    if (idx >= K1 * CC) return;
    int k = idx / CC, o = idx % CC;
    int c   = (k < CC) ? k : (k - CC);
    int tap = (k < CC) ? 1 : 0;
    g_Wf[idx] = fw[(o * CC + c) * 2 + tap];
    g_Wg[idx] = gw[(o * CC + c) * 2 + tap];
}

__global__ void pack_w2(const float* __restrict__ rw, const float* __restrict__ sw) {
    int idx = blockIdx.x * blockDim.x + threadIdx.x;
    if (idx >= CC * M2) return;
    int c = idx / M2, m = idx % M2;
    g_W2[idx] = (m < CC) ? rw[m * CC + c] : sw[(m - CC) * CC + c];
}

// ---------------- GEMM1: dilated conv pair + gating epilogue ---------------
// Block tile: 64 output channels x 128 time cols, dual accumulators (F and G).
// 128 threads = 8(m) x 16(n), each thread: 8x8 F-acc + 8x8 G-acc.
__global__ void __launch_bounds__(128)
gemm1(const float* __restrict__ x,
      const float* __restrict__ fbias, const float* __restrict__ gbias)
{
    __shared__ float sAf[2][KB][64];
    __shared__ float sAg[2][KB][64];
    __shared__ float sB [2][KB][128];

    const int nb = blockIdx.x;           // 512 n-tiles
    const int mb = blockIdx.y;           // 8 channel-tiles of 64
    const int n0 = nb * 128;
    const int b  = n0 / TT;
    const int t0 = n0 % TT;              // 8192 % 128 == 0: tile stays in one batch
    const float* __restrict__ xb = x + b * CC * TT;

    const int tid = threadIdx.x;
    const int tx  = tid & 15;            // n
    const int ty  = tid >> 4;            // m

    float accF[8][8], accG[8][8];
    #pragma unroll
    for (int i = 0; i < 8; i++)
        #pragma unroll
        for (int j = 0; j < 8; j++) { accF[i][j] = 0.f; accG[i][j] = 0.f; }

    // ---- stage loaders ----
    auto loadA = [&](int st, int k0) {
        #pragma unroll
        for (int i = 0; i < 2; i++) {
            int f4  = tid + i * 128;          // 0..255 float4s per array
            int row = f4 >> 4;                // 16 float4 per row
            int c4  = f4 & 15;
            int goff = (k0 + row) * CC + mb * 64 + c4 * 4;
            *(float4*)&sAf[st][row][c4 * 4] = *(const float4*)&g_Wf[goff];
            *(float4*)&sAg[st][row][c4 * 4] = *(const float4*)&g_Wg[goff];
        }
    };
    auto loadB = [&](int st, int k0) {
        #pragma unroll
        for (int i = 0; i < 4; i++) {
            int f4  = tid + i * 128;          // 0..511 float4s
            int row = f4 >> 5;                // 32 float4 per row
            int c4  = f4 & 31;
            int k   = k0 + row;
            float4 v;
            if (k < CC) {                     // tap1: x[t]
                v = *(const float4*)&xb[k * TT + t0 + c4 * 4];
            } else {                          // tap0: x[t-4] (causal zero pad)
                int t = t0 + c4 * 4 - DIL;
                if (t < 0) v = make_float4(0.f, 0.f, 0.f, 0.f);
                else       v = *(const float4*)&xb[(k - CC) * TT + t];
            }
            *(float4*)&sB[st][row][c4 * 4] = v;
        }
    };

    loadA(0, 0); loadB(0, 0);
    __syncthreads();

    for (int k0 = 0; k0 < K1; k0 += KB) {
        int cur = (k0 / KB) & 1, nxt = cur ^ 1;
        if (k0 + KB < K1) { loadA(nxt, k0 + KB); loadB(nxt, k0 + KB); }

        #pragma unroll
        for (int kk = 0; kk < KB; kk++) {
            float4 af0 = *(const float4*)&sAf[cur][kk][ty * 8];
            float4 af1 = *(const float4*)&sAf[cur][kk][ty * 8 + 4];
            float4 ag0 = *(const float4*)&sAg[cur][kk][ty * 8];
            float4 ag1 = *(const float4*)&sAg[cur][kk][ty * 8 + 4];
            float4 b0  = *(const float4*)&sB [cur][kk][tx * 8];
            float4 b1  = *(const float4*)&sB [cur][kk][tx * 8 + 4];
            float af[8] = {af0.x, af0.y, af0.z, af0.w, af1.x, af1.y, af1.z, af1.w};
            float ag[8] = {ag0.x, ag0.y, ag0.z, ag0.w, ag1.x, ag1.y, ag1.z, ag1.w};
            float bv[8] = {b0.x, b0.y, b0.z, b0.w, b1.x, b1.y, b1.z, b1.w};
            #pragma unroll
            for (int i = 0; i < 8; i++)
                #pragma unroll
                for (int j = 0; j < 8; j++) {
                    accF[i][j] = fmaf(af[i], bv[j], accF[i][j]);
                    accG[i][j] = fmaf(ag[i], bv[j], accG[i][j]);
                }
        }
        __syncthreads();
    }

    // ---- epilogue: z = tanh(F + bf) * sigmoid(G + bg) ----
    float* __restrict__ zb = g_z + b * CC * TT;
    #pragma unroll
    for (int i = 0; i < 8; i++) {
        int co = mb * 64 + ty * 8 + i;
        float bf = fbias[co], bg = gbias[co];
        float zr[8];
        #pragma unroll
        for (int j = 0; j < 8; j++) {
            float f = tanhf(accF[i][j] + bf);
            float g = accG[i][j] + bg;
            float s = 1.f / (1.f + __expf(-g));
            zr[j] = f * s;
        }
        float4 v0 = make_float4(zr[0], zr[1], zr[2], zr[3]);
        float4 v1 = make_float4(zr[4], zr[5], zr[6], zr[7]);
        *(float4*)&zb[co * TT + t0 + tx * 8]     = v0;
        *(float4*)&zb[co * TT + t0 + tx * 8 + 4] = v1;
    }
}

// ---------------- GEMM2: res + skip 1x1 convs, fused epilogue --------------
// Block tile: 128 rows (of 768) x 128 cols, 256 threads = 16x16, 8x8 per thread.
__global__ void __launch_bounds__(256)
gemm2(const float* __restrict__ x,
      const float* __restrict__ rbias, const float* __restrict__ sbias,
      float* __restrict__ out)
{
    __shared__ float sA[2][KB][128];
    __shared__ float sB[2][KB][128];

    const int nb = blockIdx.x;           // 512
    const int mb = blockIdx.y;           // 6
    const int n0 = nb * 128;
    const int b  = n0 / TT;
    const int t0 = n0 % TT;
    const float* __restrict__ zb = g_z + b * CC * TT;

    const int tid = threadIdx.x;
    const int tx  = tid & 15;
    const int ty  = tid >> 4;

    float acc[8][8];
    #pragma unroll
    for (int i = 0; i < 8; i++)
        #pragma unroll
        for (int j = 0; j < 8; j++) acc[i][j] = 0.f;

    auto loadA = [&](int st, int k0) {
        #pragma unroll
        for (int i = 0; i < 2; i++) {
            int f4  = tid + i * 256;          // 0..511
            int row = f4 >> 5;
            int c4  = f4 & 31;
            *(float4*)&sA[st][row][c4 * 4] =
                *(const float4*)&g_W2[(k0 + row) * M2 + mb * 128 + c4 * 4];
        }
    };
    auto loadB = [&](int st, int k0) {
        #pragma unroll
        for (int i = 0; i < 2; i++) {
            int f4  = tid + i * 256;
            int row = f4 >> 5;
            int c4  = f4 & 31;
            *(float4*)&sB[st][row][c4 * 4] =
                *(const float4*)&zb[(k0 + row) * TT + t0 + c4 * 4];
        }
    };

    loadA(0, 0); loadB(0, 0);
    __syncthreads();

    for (int k0 = 0; k0 < CC; k0 += KB) {
        int cur = (k0 / KB) & 1, nxt = cur ^ 1;
        if (k0 + KB < CC) { loadA(nxt, k0 + KB); loadB(nxt, k0 + KB); }

        #pragma unroll
        for (int kk = 0; kk < KB; kk++) {
            float4 a0 = *(const float4*)&sA[cur][kk][ty * 8];
            float4 a1 = *(const float4*)&sA[cur][kk][ty * 8 + 4];
            float4 b0 = *(const float4*)&sB[cur][kk][tx * 8];
            float4 b1 = *(const float4*)&sB[cur][kk][tx * 8 + 4];
            float av[8] = {a0.x, a0.y, a0.z, a0.w, a1.x, a1.y, a1.z, a1.w};
            float bv[8] = {b0.x, b0.y, b0.z, b0.w, b1.x, b1.y, b1.z, b1.w};
            #pragma unroll
            for (int i = 0; i < 8; i++)
                #pragma unroll
                for (int j = 0; j < 8; j++)
                    acc[i][j] = fmaf(av[i], bv[j], acc[i][j]);
        }
        __syncthreads();
    }

    // ---- epilogue: rows <512 -> (x + res + rb)*sqrt(1/2); rows >=512 -> skip + sb
    #pragma unroll
    for (int i = 0; i < 8; i++) {
        int r = mb * 128 + ty * 8 + i;
        int tcol = t0 + tx * 8;
        if (r < CC) {
            float rbv = rbias[r];
            int goff = b * CC * TT + r * TT + tcol;
            float4 x0 = *(const float4*)&x[goff];
            float4 x1 = *(const float4*)&x[goff + 4];
            float4 o0, o1;
            o0.x = (x0.x + acc[i][0] + rbv) * SQRT_HALF;
            o0.y = (x0.y + acc[i][1] + rbv) * SQRT_HALF;
            o0.z = (x0.z + acc[i][2] + rbv) * SQRT_HALF;
            o0.w = (x0.w + acc[i][3] + rbv) * SQRT_HALF;
            o1.x = (x1.x + acc[i][4] + rbv) * SQRT_HALF;
            o1.y = (x1.y + acc[i][5] + rbv) * SQRT_HALF;
            o1.z = (x1.z + acc[i][6] + rbv) * SQRT_HALF;
            o1.w = (x1.w + acc[i][7] + rbv) * SQRT_HALF;
            *(float4*)&out[goff]     = o0;
            *(float4*)&out[goff + 4] = o1;
        } else {
            int s = r - CC;
            float sbv = sbias[s];
            int goff = BB * CC * TT + b * SS * TT + s * TT + tcol;
            float4 o0 = make_float4(acc[i][0] + sbv, acc[i][1] + sbv,
                                    acc[i][2] + sbv, acc[i][3] + sbv);
            float4 o1 = make_float4(acc[i][4] + sbv, acc[i][5] + sbv,
                                    acc[i][6] + sbv, acc[i][7] + sbv);
            *(float4*)&out[goff]     = o0;
            *(float4*)&out[goff + 4] = o1;
        }
    }
}

// ---------------- launch ----------------------------------------------------
extern "C" void kernel_launch(void* const* d_in, const int* in_sizes, int n_in,
                              void* d_out, int out_size)
{
    const float* x  = (const float*)d_in[0];
    const float* fw = (const float*)d_in[1];
    const float* fb = (const float*)d_in[2];
    const float* gw = (const float*)d_in[3];
    const float* gb = (const float*)d_in[4];
    const float* rw = (const float*)d_in[5];
    const float* rb = (const float*)d_in[6];
    const float* sw = (const float*)d_in[7];
    const float* sb = (const float*)d_in[8];
    // d_in[9] = dilation (known 4, baked in)
    float* out = (float*)d_out;

    pack_w1<<<(K1 * CC + 255) / 256, 256>>>(fw, gw);
    pack_w2<<<(CC * M2 + 255) / 256, 256>>>(rw, sw);
    gemm1<<<dim3(NTOT / 128, CC / 64), 128>>>(x, fb, gb);
    gemm2<<<dim3(NTOT / 128, M2 / 128), 256>>>(x, rb, sb, out);
}

// round 4
// speedup vs baseline: 3.5794x; 3.5794x over previous
#include <cuda_runtime.h>
#include <stdint.h>
#include <math.h>

// ---------------- problem constants ----------------------------------------
#define BB   8
#define CC   512
#define SS   256
#define TT   8192
#define DIL  4
#define NTOT (BB*TT)       // 65536
#define K1   (2*CC)        // 1024 reduction dim GEMM1
#define M1   (2*CC)        // 1024 rows of W1 (F/G interleaved)
#define M2   (CC+SS)       // 768 rows GEMM2
#define KC   32            // k floats per smem stage
#define AST  36            // padded smem row stride (floats): banks (4r+c)%32 all distinct
#define SQRT_HALF 0.70710678118654752440f

// ---------------- device scratch --------------------------------------------
__device__ __align__(16) float g_xT[(size_t)NTOT*CC];  // [b][t][c], tf32-rounded
__device__ __align__(16) float g_zT[(size_t)NTOT*CC];  // [b][t][c], tf32-rounded
__device__ __align__(16) float g_W1[M1*K1];            // [o=2c+g][k], tf32-rounded
__device__ __align__(16) float g_W2[M2*CC];            // [m][k], tf32-rounded

// ---------------- helpers ----------------------------------------------------
__device__ __forceinline__ float tf32r(float x) {
    uint32_t u;
    asm("cvt.rna.tf32.f32 %0, %1;" : "=r"(u) : "f"(x));
    return __uint_as_float(u);
}

// mma.sync m16n8k8 tf32: D += A*B, fp32 accumulate
__device__ __forceinline__ void mma8(float* c, const uint32_t* a, const uint32_t* b) {
    asm volatile(
        "mma.sync.aligned.m16n8k8.row.col.f32.tf32.tf32.f32 "
        "{%0,%1,%2,%3}, {%4,%5,%6,%7}, {%8,%9}, {%0,%1,%2,%3};"
        : "+f"(c[0]), "+f"(c[1]), "+f"(c[2]), "+f"(c[3])
        : "r"(a[0]), "r"(a[1]), "r"(a[2]), "r"(a[3]), "r"(b[0]), "r"(b[1]));
}

#define STAGE (128*AST)
#define SMEM_DYN (4*STAGE*4)      // sA[2] + sB[2], bytes

// ---------------- transpose + pack ------------------------------------------
__global__ void transpose_x(const float* __restrict__ x) {
    __shared__ float tile[32][33];
    const int b = blockIdx.z, c0 = blockIdx.y * 32, t0 = blockIdx.x * 32;
    const int tx = threadIdx.x, ty = threadIdx.y;
    const float* xb = x + ((size_t)b * CC + c0) * TT + t0;
    #pragma unroll
    for (int i = 0; i < 4; i++) tile[ty + 8 * i][tx] = xb[(ty + 8 * i) * TT + tx];
    __syncthreads();
    float* xt = g_xT + ((size_t)b * TT + t0) * CC + c0;
    #pragma unroll
    for (int i = 0; i < 4; i++) xt[(ty + 8 * i) * CC + tx] = tf32r(tile[tx][ty + 8 * i]);
}

__global__ void pack_w1(const float* __restrict__ fw, const float* __restrict__ gw) {
    int idx = blockIdx.x * blockDim.x + threadIdx.x;
    if (idx >= M1 * K1) return;
    int o = idx / K1, k = idx % K1;
    int co = o >> 1;
    int ci = k & (CC - 1);
    int tap = (k < CC) ? 1 : 0;     // k<512: x[t] (tap1), k>=512: x[t-4] (tap0)
    const float* w = (o & 1) ? gw : fw;
    g_W1[idx] = tf32r(w[(co * CC + ci) * 2 + tap]);
}
__global__ void pack_w2(const float* __restrict__ rw, const float* __restrict__ sw) {
    int idx = blockIdx.x * blockDim.x + threadIdx.x;
    if (idx >= M2 * CC) return;
    int m = idx / CC, k = idx % CC;
    g_W2[idx] = tf32r((m < CC) ? rw[m * CC + k] : sw[(m - CC) * CC + k]);
}

// ---------------- GEMM1: D[t][2c+g] = xT2 @ W1^T, fused gating --------------
// CTA 128(t) x 128(interleaved outch); 8 warps 2x4; warp tile 64x32.
__global__ void __launch_bounds__(256)
gemm1(const float* __restrict__ fbias, const float* __restrict__ gbias)
{
    extern __shared__ float dsm[];
    float* sA = dsm;              // [2][128*AST]
    float* sB = dsm + 2 * STAGE;

    const int tid = threadIdx.x, lane = tid & 31, wid = tid >> 5;
    const int wm = wid >> 2, wn = wid & 3;
    const int nb = blockIdx.x;               // 8 outch-tiles
    const int tb = blockIdx.y;               // 512 t-tiles
    const int base = tb * 128;
    const int b = base / TT;
    const int t0 = base % TT;
    const int n0 = nb * 128;
    const float* __restrict__ xTb = g_xT + (size_t)b * TT * CC;

    float acc[4][4][4];
    #pragma unroll
    for (int i = 0; i < 4; i++)
        #pragma unroll
        for (int j = 0; j < 4; j++)
            #pragma unroll
            for (int q = 0; q < 4; q++) acc[i][j][q] = 0.f;

    float4 rA[4], rB[4];
    auto prefetch = [&](int k0) {
        const int sh = (k0 >= CC) ? DIL : 0;
        const int kk = k0 & (CC - 1);
        #pragma unroll
        for (int i = 0; i < 4; i++) {
            int f4 = tid + i * 256;
            int row = f4 >> 3, c4 = f4 & 7;
            int t = t0 + row - sh;
            rA[i] = (t >= 0) ? *(const float4*)&xTb[(size_t)t * CC + kk + c4 * 4]
                             : make_float4(0.f, 0.f, 0.f, 0.f);
            rB[i] = *(const float4*)&g_W1[(size_t)(n0 + row) * K1 + k0 + c4 * 4];
        }
    };
    auto store = [&](int st) {
        float* a = sA + st * STAGE;
        float* bs = sB + st * STAGE;
        #pragma unroll
        for (int i = 0; i < 4; i++) {
            int f4 = tid + i * 256;
            int row = f4 >> 3, c4 = f4 & 7;
            *(float4*)&a [row * AST + c4 * 4] = rA[i];
            *(float4*)&bs[row * AST + c4 * 4] = rB[i];
        }
    };

    prefetch(0); store(0); __syncthreads();

    const int NC = K1 / KC;   // 32
    for (int c = 0; c < NC; c++) {
        const int st = c & 1;
        if (c + 1 < NC) prefetch((c + 1) * KC);
        const float* a  = sA + st * STAGE;
        const float* bs = sB + st * STAGE;
        const int ar0 = (wm * 64 + (lane >> 2)) * AST + (lane & 3);
        const int br0 = (wn * 32 + (lane >> 2)) * AST + (lane & 3);
        #pragma unroll
        for (int ks = 0; ks < 4; ks++) {
            const int kc = ks * 8;
            uint32_t af[4][4], bf[4][2];
            #pragma unroll
            for (int mi = 0; mi < 4; mi++) {
                const float* p = a + ar0 + mi * 16 * AST + kc;
                af[mi][0] = __float_as_uint(p[0]);
                af[mi][1] = __float_as_uint(p[8 * AST]);
                af[mi][2] = __float_as_uint(p[4]);
                af[mi][3] = __float_as_uint(p[8 * AST + 4]);
            }
            #pragma unroll
            for (int ni = 0; ni < 4; ni++) {
                const float* p = bs + br0 + ni * 8 * AST + kc;
                bf[ni][0] = __float_as_uint(p[0]);
                bf[ni][1] = __float_as_uint(p[4]);
            }
            #pragma unroll
            for (int mi = 0; mi < 4; mi++)
                #pragma unroll
                for (int ni = 0; ni < 4; ni++)
                    mma8(acc[mi][ni], af[mi], bf[ni]);
        }
        if (c + 1 < NC) store(st ^ 1);
        __syncthreads();
    }

    // ---- epilogue: (c0,c1)=(F,G) of one channel at row t; (c2,c3) at t+8 ----
    const int ch_base = (n0 >> 1) + wn * 16 + (lane & 3);
    float* __restrict__ zb = g_zT + (size_t)b * TT * CC;
    #pragma unroll
    for (int mi = 0; mi < 4; mi++) {
        const int t_lo = t0 + wm * 64 + mi * 16 + (lane >> 2);
        #pragma unroll
        for (int ni = 0; ni < 4; ni++) {
            const int ch = ch_base + ni * 4;
            const float fb = fbias[ch], gb = gbias[ch];
            float F0 = acc[mi][ni][0] + fb;
            float G0 = acc[mi][ni][1] + gb;
            float F1 = acc[mi][ni][2] + fb;
            float G1 = acc[mi][ni][3] + gb;
            zb[(size_t)t_lo * CC + ch] =
                tf32r(tanhf(F0) * (1.f / (1.f + __expf(-G0))));
            zb[(size_t)(t_lo + 8) * CC + ch] =
                tf32r(tanhf(F1) * (1.f / (1.f + __expf(-G1))));
        }
    }
}

// ---------------- GEMM2: D[m][t] = W2 @ zT^T, fused residual/skip -----------
// CTA 128(m) x 128(t); 8 warps 2x4; warp tile 64x32.
__global__ void __launch_bounds__(256)
gemm2(const float* __restrict__ x,
      const float* __restrict__ rbias, const float* __restrict__ sbias,
      float* __restrict__ out)
{
    extern __shared__ float dsm[];
    float* sA = dsm;
    float* sB = dsm + 2 * STAGE;

    const int tid = threadIdx.x, lane = tid & 31, wid = tid >> 5;
    const int wm = wid >> 2, wn = wid & 3;
    const int mb = blockIdx.x;               // 6 m-tiles
    const int tb = blockIdx.y;               // 512 t-tiles
    const int base = tb * 128;
    const int b = base / TT;
    const int t0 = base % TT;
    const int m0 = mb * 128;
    const float* __restrict__ zTb = g_zT + (size_t)b * TT * CC;

    float acc[4][4][4];
    #pragma unroll
    for (int i = 0; i < 4; i++)
        #pragma unroll
        for (int j = 0; j < 4; j++)
            #pragma unroll
            for (int q = 0; q < 4; q++) acc[i][j][q] = 0.f;

    float4 rA[4], rB[4];
    auto prefetch = [&](int k0) {
        #pragma unroll
        for (int i = 0; i < 4; i++) {
            int f4 = tid + i * 256;
            int row = f4 >> 3, c4 = f4 & 7;
            rA[i] = *(const float4*)&g_W2[(size_t)(m0 + row) * CC + k0 + c4 * 4];
            rB[i] = *(const float4*)&zTb[(size_t)(t0 + row) * CC + k0 + c4 * 4];
        }
    };
    auto store = [&](int st) {
        float* a = sA + st * STAGE;
        float* bs = sB + st * STAGE;
        #pragma unroll
        for (int i = 0; i < 4; i++) {
            int f4 = tid + i * 256;
            int row = f4 >> 3, c4 = f4 & 7;
            *(float4*)&a [row * AST + c4 * 4] = rA[i];
            *(float4*)&bs[row * AST + c4 * 4] = rB[i];
        }
    };

    prefetch(0); store(0); __syncthreads();

    const int NC = CC / KC;   // 16
    for (int c = 0; c < NC; c++) {
        const int st = c & 1;
        if (c + 1 < NC) prefetch((c + 1) * KC);
        const float* a  = sA + st * STAGE;
        const float* bs = sB + st * STAGE;
        const int ar0 = (wm * 64 + (lane >> 2)) * AST + (lane & 3);
        const int br0 = (wn * 32 + (lane >> 2)) * AST + (lane & 3);
        #pragma unroll
        for (int ks = 0; ks < 4; ks++) {
            const int kc = ks * 8;
            uint32_t af[4][4], bf[4][2];
            #pragma unroll
            for (int mi = 0; mi < 4; mi++) {
                const float* p = a + ar0 + mi * 16 * AST + kc;
                af[mi][0] = __float_as_uint(p[0]);
                af[mi][1] = __float_as_uint(p[8 * AST]);
                af[mi][2] = __float_as_uint(p[4]);
                af[mi][3] = __float_as_uint(p[8 * AST + 4]);
            }
            #pragma unroll
            for (int ni = 0; ni < 4; ni++) {
                const float* p = bs + br0 + ni * 8 * AST + kc;
                bf[ni][0] = __float_as_uint(p[0]);
                bf[ni][1] = __float_as_uint(p[4]);
            }
            #pragma unroll
            for (int mi = 0; mi < 4; mi++)
                #pragma unroll
                for (int ni = 0; ni < 4; ni++)
                    mma8(acc[mi][ni], af[mi], bf[ni]);
        }
        if (c + 1 < NC) store(st ^ 1);
        __syncthreads();
    }

    // ---- epilogue: rows m (channels), cols t; float2 per (row, ni) ----------
    #pragma unroll
    for (int mi = 0; mi < 4; mi++) {
        const int m_lo = m0 + wm * 64 + mi * 16 + (lane >> 2);
        #pragma unroll
        for (int half = 0; half < 2; half++) {
            const int m = m_lo + half * 8;
            if (m < CC) {
                const float rbv = rbias[m];
                const float* __restrict__ xrow = x + ((size_t)b * CC + m) * TT;
                float* __restrict__ orow = out + ((size_t)b * CC + m) * TT;
                #pragma unroll
                for (int ni = 0; ni < 4; ni++) {
                    const int t = t0 + wn * 32 + ni * 8 + (lane & 3) * 2;
                    float2 xv = *(const float2*)&xrow[t];
                    float2 o;
                    o.x = (xv.x + acc[mi][ni][half * 2]     + rbv) * SQRT_HALF;
                    o.y = (xv.y + acc[mi][ni][half * 2 + 1] + rbv) * SQRT_HALF;
                    *(float2*)&orow[t] = o;
                }
            } else {
                const int s = m - CC;
                const float sbv = sbias[s];
                float* __restrict__ orow =
                    out + (size_t)BB * CC * TT + ((size_t)b * SS + s) * TT;
                #pragma unroll
                for (int ni = 0; ni < 4; ni++) {
                    const int t = t0 + wn * 32 + ni * 8 + (lane & 3) * 2;
                    float2 o;
                    o.x = acc[mi][ni][half * 2]     + sbv;
                    o.y = acc[mi][ni][half * 2 + 1] + sbv;
                    *(float2*)&orow[t] = o;
                }
            }
        }
    }
}

// ---------------- launch -----------------------------------------------------
extern "C" void kernel_launch(void* const* d_in, const int* in_sizes, int n_in,
                              void* d_out, int out_size)
{
    const float* x  = (const float*)d_in[0];
    const float* fw = (const float*)d_in[1];
    const float* fb = (const float*)d_in[2];
    const float* gw = (const float*)d_in[3];
    const float* gb = (const float*)d_in[4];
    const float* rw = (const float*)d_in[5];
    const float* rb = (const float*)d_in[6];
    const float* sw = (const float*)d_in[7];
    const float* sb = (const float*)d_in[8];
    float* out = (float*)d_out;

    cudaFuncSetAttribute(gemm1, cudaFuncAttributeMaxDynamicSharedMemorySize, SMEM_DYN);
    cudaFuncSetAttribute(gemm2, cudaFuncAttributeMaxDynamicSharedMemorySize, SMEM_DYN);

    transpose_x<<<dim3(TT / 32, CC / 32, BB), dim3(32, 8)>>>(x);
    pack_w1<<<(M1 * K1 + 255) / 256, 256>>>(fw, gw);
    pack_w2<<<(M2 * CC + 255) / 256, 256>>>(rw, sw);
    gemm1<<<dim3(M1 / 128, NTOT / 128), 256, SMEM_DYN>>>(fb, gb);
    gemm2<<<dim3(M2 / 128, NTOT / 128), 256, SMEM_DYN>>>(x, rb, sb, out);
}